// round 7
// baseline (speedup 1.0000x reference)
#include <cuda_runtime.h>
#include <cstdint>

// out[o,m,n] = sum_{kh,j} w0[o,kh,j] * S[m, n+kh, j]       (n >= 1)
// out[o,m,0] = sum_{kh,j} w0[o,kh,j] * S0[m, kh, j]
// Scratch: Sg[((m*14 + j)*80) + r], r in [0,63] = S rows, [64,72] = S0 rows.

__device__ __align__(16) float Sg[56 * 14 * 80];

__device__ __forceinline__ uint64_t pack2(float s) {
    uint64_t r;
    unsigned u = __float_as_uint(s);
    asm("mov.b64 %0, {%1, %1};" : "=l"(r) : "r"(u));
    return r;
}
__device__ __forceinline__ void ffma2(uint64_t& d, uint64_t a, uint64_t b) {
    asm("fma.rn.f32x2 %0, %1, %2, %0;" : "+l"(d) : "l"(a), "l"(b));
}
__device__ __forceinline__ float2 unpack2(uint64_t v) {
    unsigned lo, hi;
    asm("mov.b64 {%0, %1}, %2;" : "=r"(lo), "=r"(hi) : "l"(v));
    return make_float2(__uint_as_float(lo), __uint_as_float(hi));
}

// ───────────── Kernel 1: build S ─────────────
#define XP 68
__global__ __launch_bounds__(160)
void build_S_kernel(const float* __restrict__ x, const float* __restrict__ w1)
{
    __shared__ float xp[24 * XP];   // xp[i][h+5] = x[i,m,h], pads zero
    __shared__ float w1s[24 * 28];
    const int m = blockIdx.x, jg = blockIdx.y, tid = threadIdx.x;

    for (int t = tid; t < 24 * XP; t += 160) xp[t] = 0.0f;
    for (int t = tid; t < 24 * 28; t += 160) w1s[t] = w1[t];
    __syncthreads();
    for (int t = tid; t < 24 * 56; t += 160) {
        const int i = t / 56, h = t % 56;
        xp[i * XP + 5 + h] = x[i * 3136 + m * 56 + h];
    }
    __syncthreads();

    if (tid < 146) {
        const int j = jg * 2 + tid / 73;
        const int r = tid % 73;
        float a0 = 0.f, a1 = 0.f, a2 = 0.f, a3 = 0.f;
        if (r < 64) {
            #pragma unroll
            for (int i = 0; i < 24; i += 2) {
                a0 = fmaf(xp[i * XP + r + 1],       w1s[i * 28 + j],            a0);
                a1 = fmaf(xp[i * XP + r],           w1s[i * 28 + 14 + j],       a1);
                a2 = fmaf(xp[(i+1) * XP + r + 1],   w1s[(i+1) * 28 + j],        a2);
                a3 = fmaf(xp[(i+1) * XP + r],       w1s[(i+1) * 28 + 14 + j],   a3);
            }
        } else {
            const int kh = r - 64;
            if (kh >= 4) {
                #pragma unroll
                for (int i = 0; i < 24; i += 2) {
                    a0 = fmaf(xp[i * XP + kh + 1],     w1s[i * 28 + j],     a0);
                    a2 = fmaf(xp[(i+1) * XP + kh + 1], w1s[(i+1) * 28 + j], a2);
                }
            }
            if (kh <= 4) {
                #pragma unroll
                for (int i = 0; i < 24; i += 2) {
                    a1 = fmaf(xp[i * XP + kh + 56],     w1s[i * 28 + 14 + j],     a1);
                    a3 = fmaf(xp[(i+1) * XP + kh + 56], w1s[(i+1) * 28 + 14 + j], a3);
                }
            }
        }
        Sg[(m * 14 + j) * 80 + r] = (a0 + a2) + (a1 + a3);
    }
}

// ───────────── Kernel 2: contraction ─────────────
// grid (56 m, 12 og of 8 o), block 224 = ow(2) × jh(2) × n(56).
// Each thread: 4 o's, 7 j's (jh half), 9 kh -> 63 iters of {LDS.64 s-dup, LDS.128 w, 2 FFMA2}.
// jh halves combined via shfl_xor(2).
#define SJ 81   // Sd row stride in u64 (makes jh pairs bank-disjoint)
__global__ __launch_bounds__(224, 5)
void contract_kernel(const float* __restrict__ w0, float* __restrict__ out)
{
    __shared__ __align__(16) uint64_t Sd[14 * SJ];     // 9.1 KB, dup-pair S
    __shared__ __align__(16) float w0s[126 * 8];       // 4 KB, [k][8 o]

    const int m   = blockIdx.x;
    const int og  = blockIdx.y;          // 0..11
    const int tid = threadIdx.x;

    // stage S slice (coalesced float reads, dup-pair writes)
    for (int t = tid; t < 14 * 80; t += 224) {
        const int j = t / 80, r = t % 80;
        Sd[j * SJ + r] = pack2(Sg[m * 1120 + t]);
    }
    // stage w0 transposed, k-major GMEM reads (coalesced)
    for (int t = tid; t < 126 * 8; t += 224) {
        const int k = t % 126, ol = t / 126;
        w0s[k * 8 + ol] = w0[(og * 8 + ol) * 126 + k];
    }
    __syncthreads();

    const int ow = tid & 1;                  // 2 o-quads
    const int jh = (tid >> 1) & 1;           // j half
    const int n  = tid >> 2;                 // 0..55
    const int rbase = (n == 0) ? 64 : n;
    const int jbase = jh * 7;

    const uint64_t* __restrict__ sp = Sd + jbase * SJ + rbase;
    const ulonglong2* __restrict__ wp =
        reinterpret_cast<const ulonglong2*>(w0s) + ow;     // index k*2 + ow

    uint64_t acc0 = 0, acc1 = 0;
    #pragma unroll
    for (int j = 0; j < 7; j++) {
        uint64_t svd[9];
        #pragma unroll
        for (int kh = 0; kh < 9; kh++)
            svd[kh] = sp[j * SJ + kh];
        #pragma unroll
        for (int g = 0; g < 9; g += 3) {
            const ulonglong2 wa = wp[((g + 0) * 14 + jbase + j) * 2];
            const ulonglong2 wb = wp[((g + 1) * 14 + jbase + j) * 2];
            const ulonglong2 wc = wp[((g + 2) * 14 + jbase + j) * 2];
            ffma2(acc0, wa.x, svd[g + 0]); ffma2(acc1, wa.y, svd[g + 0]);
            ffma2(acc0, wb.x, svd[g + 1]); ffma2(acc1, wb.y, svd[g + 1]);
            ffma2(acc0, wc.x, svd[g + 2]); ffma2(acc1, wc.y, svd[g + 2]);
        }
    }

    // combine jh halves (lane bit 1)
    float2 a0 = unpack2(acc0), a1 = unpack2(acc1);
    a0.x += __shfl_xor_sync(0xffffffffu, a0.x, 2);
    a0.y += __shfl_xor_sync(0xffffffffu, a0.y, 2);
    a1.x += __shfl_xor_sync(0xffffffffu, a1.x, 2);
    a1.y += __shfl_xor_sync(0xffffffffu, a1.y, 2);

    if (jh == 0) {
        const int ob = og * 8 + ow * 4;
        float* op = out + m * 56 + n;
        op[(ob + 0) * 3136] = a0.x;
        op[(ob + 1) * 3136] = a0.y;
        op[(ob + 2) * 3136] = a1.x;
        op[(ob + 3) * 3136] = a1.y;
    }
}

extern "C" void kernel_launch(void* const* d_in, const int* in_sizes, int n_in,
                              void* d_out, int out_size)
{
    const float* x = (const float*)d_in[0];
    const float* w0;
    const float* w1;
    if (in_sizes[1] == 12096) { w0 = (const float*)d_in[1]; w1 = (const float*)d_in[2]; }
    else                      { w0 = (const float*)d_in[2]; w1 = (const float*)d_in[1]; }
    float* out = (float*)d_out;

    build_S_kernel<<<dim3(56, 7), 160>>>(x, w1);
    contract_kernel<<<dim3(56, 12), 224>>>(w0, out);
}